// round 3
// baseline (speedup 1.0000x reference)
#include <cuda_runtime.h>
#include <stdint.h>

// Problem constants (fixed by setup_inputs): B=32, T=512, dur < 16.
#define B_SZ 32
#define T_SZ 512
#define M_MAX (T_SZ * 15)   // worst-case frames per row = 7680

// frame -> token map, -1 for padding frames. Scratch as __device__ global
// (no allocations allowed). 32 * 7680 * 4B ~= 3.9 MB.
__device__ int g_f2t[B_SZ * M_MAX];

// Kernel A: one block per batch row. Inclusive scan of durations, then each
// token scatters its index over its frame range. Frames >= total stay -1.
__global__ void __launch_bounds__(T_SZ) build_f2t_kernel(
    const int* __restrict__ dur, int M)
{
    __shared__ int s[T_SZ];
    const int b = blockIdx.x;
    const int t = threadIdx.x;

    const int d = dur[b * T_SZ + t];
    s[t] = d;
    __syncthreads();

    // Hillis-Steele inclusive scan over 512 elements.
    #pragma unroll
    for (int off = 1; off < T_SZ; off <<= 1) {
        int v = s[t];
        if (t >= off) v += s[t - off];
        __syncthreads();
        s[t] = v;
        __syncthreads();
    }

    const int end   = s[t];
    const int start = end - d;

    // Init this row's map to -1 (covers frames [total, M)).
    int* row = g_f2t + (size_t)b * M;
    for (int f = t; f < M; f += T_SZ) row[f] = -1;
    __syncthreads();

    // Scatter: token t owns frames [start, end). d <= 15.
    for (int f = start; f < end; f++) row[f] = t;
}

// Kernel B: one thread per float4 of the [B, M, T] output.
// row index (b*M + f) = idx >> 7 since T/4 = 128.
__global__ void __launch_bounds__(256) write_align_kernel(
    float4* __restrict__ out, long long n4)
{
    const long long idx = (long long)blockIdx.x * blockDim.x + threadIdx.x;
    if (idx >= n4) return;

    const long long row = idx >> 7;          // (b, f) flat index
    const int tok = __ldg(&g_f2t[row]);      // broadcast within the 128-thread row
    const int t0  = ((int)idx & 127) << 2;   // first token column of this float4

    float4 v;
    v.x = (t0     == tok) ? 1.0f : 0.0f;
    v.y = (t0 + 1 == tok) ? 1.0f : 0.0f;
    v.z = (t0 + 2 == tok) ? 1.0f : 0.0f;
    v.w = (t0 + 3 == tok) ? 1.0f : 0.0f;
    out[idx] = v;
}

extern "C" void kernel_launch(void* const* d_in, const int* in_sizes, int n_in,
                              void* d_out, int out_size)
{
    const int* dur = (const int*)d_in[0];

    // out is [B, M, T] float32; derive M from out_size.
    const int M = out_size / (B_SZ * T_SZ);

    // Resolve the device-global scratch address is implicit (static symbol).
    build_f2t_kernel<<<B_SZ, T_SZ>>>(dur, M);

    const long long n4 = (long long)out_size / 4;   // T=512 divisible by 4
    const int threads = 256;
    const long long blocks = (n4 + threads - 1) / threads;
    write_align_kernel<<<(unsigned)blocks, threads>>>((float4*)d_out, n4);
}

// round 4
// speedup vs baseline: 1.4083x; 1.4083x over previous
#include <cuda_runtime.h>
#include <stdint.h>

// Problem constants (fixed by setup_inputs): B=32, T=512, dur < 16.
#define B_SZ 32
#define T_SZ 512
#define M_MAX (T_SZ * 15)   // worst-case frames per row = 7680

// frame -> token map, -1 for padding frames. Scratch as __device__ global.
__device__ int g_f2t[B_SZ * M_MAX];

// Kernel A: one block per batch row. Inclusive scan of durations, then each
// token scatters its index over its frame range. Frames >= total stay -1.
__global__ void __launch_bounds__(T_SZ) build_f2t_kernel(
    const int* __restrict__ dur, int M)
{
    __shared__ int s[T_SZ];
    const int b = blockIdx.x;
    const int t = threadIdx.x;

    const int d = dur[b * T_SZ + t];
    s[t] = d;
    __syncthreads();

    #pragma unroll
    for (int off = 1; off < T_SZ; off <<= 1) {
        int v = s[t];
        if (t >= off) v += s[t - off];
        __syncthreads();
        s[t] = v;
        __syncthreads();
    }

    const int end   = s[t];
    const int start = end - d;

    int* row = g_f2t + (size_t)b * M;
    for (int f = t; f < M; f += T_SZ) row[f] = -1;
    __syncthreads();

    for (int f = start; f < end; f++) row[f] = t;
}

// Kernel B v2: each block writes a contiguous 1024-float4 (16 KB) chunk.
// 256 threads x 4 float4 each at +k*256 strides -> every STG.128 coalesced,
// 4 independent LDG->STG chains per thread for MLP. n4 is guaranteed a
// multiple of 1024 (n4 = 4096*M), so no bounds checks.
// Stores use streaming hint (evict-first): output has zero reuse.
__global__ void __launch_bounds__(256) write_align_kernel4(
    float4* __restrict__ out)
{
    const long long base = (long long)blockIdx.x * 1024 + threadIdx.x;

    #pragma unroll
    for (int k = 0; k < 4; k++) {
        const long long idx = base + k * 256;
        const long long row = idx >> 7;          // (b, f) flat index; T/4 = 128
        const int tok = __ldg(&g_f2t[row]);      // warp-uniform -> broadcast
        const int t0  = ((int)idx & 127) << 2;   // first token column

        float4 v;
        v.x = (t0     == tok) ? 1.0f : 0.0f;
        v.y = (t0 + 1 == tok) ? 1.0f : 0.0f;
        v.z = (t0 + 2 == tok) ? 1.0f : 0.0f;
        v.w = (t0 + 3 == tok) ? 1.0f : 0.0f;
        __stcs(&out[idx], v);
    }
}

// Fallback (guarded, 1 float4/thread) for any shape where n4 % 1024 != 0.
__global__ void __launch_bounds__(256) write_align_kernel1(
    float4* __restrict__ out, long long n4)
{
    const long long idx = (long long)blockIdx.x * blockDim.x + threadIdx.x;
    if (idx >= n4) return;
    const long long row = idx >> 7;
    const int tok = __ldg(&g_f2t[row]);
    const int t0  = ((int)idx & 127) << 2;
    float4 v;
    v.x = (t0     == tok) ? 1.0f : 0.0f;
    v.y = (t0 + 1 == tok) ? 1.0f : 0.0f;
    v.z = (t0 + 2 == tok) ? 1.0f : 0.0f;
    v.w = (t0 + 3 == tok) ? 1.0f : 0.0f;
    __stcs(&out[idx], v);
}

extern "C" void kernel_launch(void* const* d_in, const int* in_sizes, int n_in,
                              void* d_out, int out_size)
{
    const int* dur = (const int*)d_in[0];

    // out is [B, M, T] float32; derive M from out_size.
    const int M = out_size / (B_SZ * T_SZ);

    build_f2t_kernel<<<B_SZ, T_SZ>>>(dur, M);

    const long long n4 = (long long)out_size / 4;
    if ((n4 & 1023) == 0) {
        write_align_kernel4<<<(unsigned)(n4 >> 10), 256>>>((float4*)d_out);
    } else {
        const long long blocks = (n4 + 255) / 256;
        write_align_kernel1<<<(unsigned)blocks, 256>>>((float4*)d_out, n4);
    }
}

// round 5
// speedup vs baseline: 1.4317x; 1.0166x over previous
#include <cuda_runtime.h>
#include <stdint.h>

// Problem constants (fixed by setup_inputs): B=32, T=512, dur < 16.
#define B_SZ 32
#define T_SZ 512
#define M_MAX (T_SZ * 15)   // worst-case frames per row = 7680

// frame -> token map, -1 for padding frames. Scratch as __device__ global.
__device__ int g_f2t[B_SZ * M_MAX];

// Kernel A: one block per batch row. Warp-shuffle inclusive scan of the 512
// durations (16 warp partials + warp-0 scan), then each token scatters its
// index over its frame range. Frames >= total stay -1.
__global__ void __launch_bounds__(T_SZ) build_f2t_kernel(
    const int* __restrict__ dur, int M)
{
    __shared__ int warp_sum[16];
    const int b    = blockIdx.x;
    const int t    = threadIdx.x;
    const int lane = t & 31;
    const int wid  = t >> 5;

    const int d = dur[b * T_SZ + t];

    // Warp inclusive scan.
    int v = d;
    #pragma unroll
    for (int off = 1; off < 32; off <<= 1) {
        int u = __shfl_up_sync(0xFFFFFFFF, v, off);
        if (lane >= off) v += u;
    }
    if (lane == 31) warp_sum[wid] = v;
    __syncthreads();

    // Warp 0 scans the 16 warp totals (exclusive offsets back to smem).
    if (wid == 0 && lane < 16) {
        int s = warp_sum[lane];
        #pragma unroll
        for (int off = 1; off < 16; off <<= 1) {
            int u = __shfl_up_sync(0xFFFF, s, off);
            if (lane >= off) s += u;
        }
        warp_sum[lane] = s - warp_sum[lane];   // exclusive
    }
    __syncthreads();

    const int end   = v + warp_sum[wid];
    const int start = end - d;

    int* row = g_f2t + b * M;
    for (int f = t; f < M; f += T_SZ) row[f] = -1;
    __syncthreads();

    for (int f = start; f < end; f++) row[f] = t;
}

// Kernel B v3: one warp per output row. Block = 8 warps = 8 rows = 1024
// float4 (16 KB). Each lane loads tok ONCE, then issues 4 independent
// coalesced STG.128 at columns lane + 32*j. All 32-bit index math.
// n4 = 4096*M is always a multiple of 1024.
__global__ void __launch_bounds__(256) write_align_kernel_warprow(
    float4* __restrict__ out)
{
    const int lane = threadIdx.x & 31;
    const int wid  = threadIdx.x >> 5;
    const int row  = blockIdx.x * 8 + wid;       // flat (b, f) index, < 32*M

    const int tok = __ldg(&g_f2t[row]);          // warp-uniform broadcast

    float4* rp = out + (unsigned)row * 128u;     // row base (128 float4)

    #pragma unroll
    for (int j = 0; j < 4; j++) {
        const int c  = lane + 32 * j;            // float4 column in row
        const int t0 = c << 2;                   // first token column
        float4 v;
        v.x = (t0     == tok) ? 1.0f : 0.0f;
        v.y = (t0 + 1 == tok) ? 1.0f : 0.0f;
        v.z = (t0 + 2 == tok) ? 1.0f : 0.0f;
        v.w = (t0 + 3 == tok) ? 1.0f : 0.0f;
        __stcs(&rp[c], v);
    }
}

// Fallback (guarded, 1 float4/thread) for any shape where n4 % 1024 != 0.
__global__ void __launch_bounds__(256) write_align_kernel1(
    float4* __restrict__ out, long long n4)
{
    const long long idx = (long long)blockIdx.x * blockDim.x + threadIdx.x;
    if (idx >= n4) return;
    const long long row = idx >> 7;
    const int tok = __ldg(&g_f2t[row]);
    const int t0  = ((int)idx & 127) << 2;
    float4 v;
    v.x = (t0     == tok) ? 1.0f : 0.0f;
    v.y = (t0 + 1 == tok) ? 1.0f : 0.0f;
    v.z = (t0 + 2 == tok) ? 1.0f : 0.0f;
    v.w = (t0 + 3 == tok) ? 1.0f : 0.0f;
    __stcs(&out[idx], v);
}

extern "C" void kernel_launch(void* const* d_in, const int* in_sizes, int n_in,
                              void* d_out, int out_size)
{
    const int* dur = (const int*)d_in[0];

    // out is [B, M, T] float32; derive M from out_size.
    const int M = out_size / (B_SZ * T_SZ);

    build_f2t_kernel<<<B_SZ, T_SZ>>>(dur, M);

    const long long n4 = (long long)out_size / 4;
    if ((n4 & 1023) == 0) {
        write_align_kernel_warprow<<<(unsigned)(n4 >> 10), 256>>>((float4*)d_out);
    } else {
        const long long blocks = (n4 + 255) / 256;
        write_align_kernel1<<<(unsigned)blocks, 256>>>((float4*)d_out, n4);
    }
}